// round 6
// baseline (speedup 1.0000x reference)
#include <cuda_runtime.h>
#include <math.h>

#define BB  128   // batch
#define TT  256   // time steps
#define TD  256   // feature dim D
#define NS  32    // stack depth

// ---------------------------------------------------------------------------
// Device scratch (no allocations allowed)
// ---------------------------------------------------------------------------
__device__ float  g_scratch[BB * TT];            // latch gates g[b][t]
__device__ float4 coef_buf[BB * TT * NS];        // per-(b,t,slot): {a, e, c, w}

// ---------------------------------------------------------------------------
// K1: g[b][t] = elu(cos_sim(latch_enable, x[b,t,:])). One warp per (b,t).
// ---------------------------------------------------------------------------
__global__ void __launch_bounds__(256) precompute_g_kernel(
    const float* __restrict__ x,
    const float* __restrict__ le)
{
    const int warp = threadIdx.x >> 5;
    const int lane = threadIdx.x & 31;
    const int bt   = blockIdx.x * 8 + warp;
    const float* xp = x + (size_t)bt * TD;

    float dot = 0.f, nx = 0.f, nl = 0.f;
#pragma unroll
    for (int k = 0; k < 8; k++) {
        float xv = xp[lane + k * 32];
        float lv = le[lane + k * 32];
        dot = fmaf(lv, xv, dot);
        nx  = fmaf(xv, xv, nx);
        nl  = fmaf(lv, lv, nl);
    }
#pragma unroll
    for (int o = 16; o; o >>= 1) {
        dot += __shfl_xor_sync(0xffffffffu, dot, o);
        nx  += __shfl_xor_sync(0xffffffffu, nx,  o);
        nl  += __shfl_xor_sync(0xffffffffu, nl,  o);
    }
    if (lane == 0) {
        float an = fmaxf(sqrtf(nl), 1e-8f);
        float bn = fmaxf(sqrtf(nx), 1e-8f);
        float c  = dot / (an * bn);
        g_scratch[bt] = (c > 0.f) ? c : expm1f(c);
    }
}

// ---------------------------------------------------------------------------
// K2: fused latch + pop + pointer recurrence. ONE WARP per batch, no barriers.
// Lane n owns pointer slot n (unnormalized q). Lane l owns latch dims
// [l*8, l*8+8). Deferred normalization: sigma reduction + coef store for step
// t-1 happen at the top of iteration t, overlapping the pop chain.
// Emits coef_buf[b][t][n] = {a, e, c, w=pop*p_new}.
// ---------------------------------------------------------------------------
__global__ void __launch_bounds__(32) pointer_scan_kernel(
    const float* __restrict__ x,
    const float* __restrict__ should_pop,
    const float* __restrict__ sharpen_ptr,
    const float* __restrict__ latch_init)
{
    const int b    = blockIdx.x;
    const int lane = threadIdx.x;
    const unsigned FULL = 0xffffffffu;

    const float sharpen = sharpen_ptr[0];

    // per-lane latch dims d = lane*8 + j
    float4 spA = *(const float4*)(should_pop + lane * 8);
    float4 spB = *(const float4*)(should_pop + lane * 8 + 4);
    float4 lA  = *(const float4*)(latch_init + b * TD + lane * 8);
    float4 lB  = *(const float4*)(latch_init + b * TD + lane * 8 + 4);

    // |sp| norm (once)
    float sp2 = spA.x*spA.x + spA.y*spA.y + spA.z*spA.z + spA.w*spA.w
              + spB.x*spB.x + spB.y*spB.y + spB.z*spB.z + spB.w*spB.w;
#pragma unroll
    for (int o = 16; o; o >>= 1) sp2 += __shfl_xor_sync(FULL, sp2, o);
    const float inv_an = 1.0f / fmaxf(sqrtf(sp2), 1e-8f);

    // r0 = sp.latch, r1 = |latch|^2  (for pop at t=0, uses latch_init)
    float r0 = spA.x*lA.x + spA.y*lA.y + spA.z*lA.z + spA.w*lA.w
             + spB.x*lB.x + spB.y*lB.y + spB.z*lB.z + spB.w*lB.w;
    float r1 = lA.x*lA.x + lA.y*lA.y + lA.z*lA.z + lA.w*lA.w
             + lB.x*lB.x + lB.y*lB.y + lB.z*lB.z + lB.w*lB.w;
#pragma unroll
    for (int o = 16; o; o >>= 1) {
        r0 += __shfl_xor_sync(FULL, r0, o);
        r1 += __shfl_xor_sync(FULL, r1, o);
    }

    // unnormalized pointer; initial: slot0 = 1.0, others 1e-6; sigma0 = 1 exact
    float q = (lane == 0) ? 1.0f : 1e-6f;

    const float*  gb  = g_scratch + b * TT;
    const float4* xb4 = (const float4*)(x + (size_t)b * TT * TD);
    float4*       cb  = coef_buf + (size_t)b * TT * NS;

    float pop_prev = 0.f, a_prev = 0.f, e_prev = 0.f, c_prev = 0.f;

    for (int t = 0; t < TT; t++) {
        // ---- sigma reduce on q (= q_{t-1}) interleaved with pop_t chain ----
        float s = q;
        float bn = fmaxf(sqrtf(r1), 1e-8f);
        s += __shfl_xor_sync(FULL, s, 1);
        float cosv = r0 * inv_an / bn;
        s += __shfl_xor_sync(FULL, s, 2);
        float pop = (cosv > 0.f) ? cosv : expm1f(cosv);
        s += __shfl_xor_sync(FULL, s, 4);
        float push = 1.0f - pop;
        s += __shfl_xor_sync(FULL, s, 8);
        s += __shfl_xor_sync(FULL, s, 16);
        float sg   = (t == 0) ? 1.0f : fmaxf(s, 1e-8f);   // ref uses raw ptr0 at t=0
        float invs = 1.0f / sg;
        float lgs  = __log2f(sg);

        // ---- deferred store of step t-1 coefs (w needed sigma_{t-1}) ----
        if (t > 0) {
            float w = pop_prev * q * invs;
            cb[(t - 1) * NS + lane] = make_float4(a_prev, e_prev, c_prev, w);
        }

        // ---- pointer mix & coefs for step t (p_{t-1} = q * invs) ----
        float qp = __shfl_sync(FULL, q, (lane + 31) & 31);  // p_push (roll +1)
        float qm = __shfl_sync(FULL, q, (lane + 1) & 31);   // p_pop  (roll -1)
        float npu = push * qp + pop * qm;                   // sigma * new_ptr
        float e = push * (qp * invs);
        float f = pop  * (q  * invs);
        float a = 1.0f - e - f;
        float c = 1e-6f * f;

        // ---- sharpen with deferred normalization: qn = (npu/sigma)^sharpen ----
        float qn = (npu > 0.f) ? exp2f(sharpen * (__log2f(npu) - lgs)) : 0.f;

        // ---- latch update (g-driven, independent of pop) + next r reduce ----
        float gg = gb[t];
        float4 xa = xb4[t * (TD / 4) + lane * 2];
        float4 xc = xb4[t * (TD / 4) + lane * 2 + 1];
        lA.x = fmaf(gg, xa.x - lA.x, lA.x);
        lA.y = fmaf(gg, xa.y - lA.y, lA.y);
        lA.z = fmaf(gg, xa.z - lA.z, lA.z);
        lA.w = fmaf(gg, xa.w - lA.w, lA.w);
        lB.x = fmaf(gg, xc.x - lB.x, lB.x);
        lB.y = fmaf(gg, xc.y - lB.y, lB.y);
        lB.z = fmaf(gg, xc.z - lB.z, lB.z);
        lB.w = fmaf(gg, xc.w - lB.w, lB.w);

        float p0 = spA.x*lA.x + spA.y*lA.y + spA.z*lA.z + spA.w*lA.w
                 + spB.x*lB.x + spB.y*lB.y + spB.z*lB.z + spB.w*lB.w;
        float p1 = lA.x*lA.x + lA.y*lA.y + lA.z*lA.z + lA.w*lA.w
                 + lB.x*lB.x + lB.y*lB.y + lB.z*lB.z + lB.w*lB.w;
#pragma unroll
        for (int o = 16; o; o >>= 1) {
            p0 += __shfl_xor_sync(FULL, p0, o);
            p1 += __shfl_xor_sync(FULL, p1, o);
        }
        r0 = p0; r1 = p1;

        // rotate pipeline registers
        q = qn;
        pop_prev = pop; a_prev = a; e_prev = e; c_prev = c;
    }

    // ---- final store for t = 255 ----
    {
        float s = q;
#pragma unroll
        for (int o = 16; o; o >>= 1) s += __shfl_xor_sync(FULL, s, o);
        float invs = 1.0f / fmaxf(s, 1e-8f);
        float w = pop_prev * q * invs;
        cb[(TT - 1) * NS + lane] = make_float4(a_prev, e_prev, c_prev, w);
    }
}

// ---------------------------------------------------------------------------
// K3: stack recurrence. Thread = (batch, 2 d-columns). No communication,
// no barriers. Per step: 32 broadcast LDG.128 coef + 192 FMA.
// ---------------------------------------------------------------------------
__global__ void __launch_bounds__(128) stack_kernel(
    const float* __restrict__ x,
    float* __restrict__ out)
{
    const int b = blockIdx.x;
    const int i = threadIdx.x;

    const float4* cb = coef_buf + (size_t)b * TT * NS;
    const float*  xb = x   + (size_t)b * TT * TD;
    float*        ob = out + (size_t)b * TT * TD;

    float st0[NS], st1[NS];
#pragma unroll
    for (int n = 0; n < NS; n++) { st0[n] = 1e-6f; st1[n] = 1e-6f; }

    for (int t = 0; t < TT; t++) {
        const float in0 = xb[t * TD + i];
        const float in1 = xb[t * TD + i + 128];
        const float4* cf = cb + t * NS;
        float s0 = 0.f, s1 = 0.f;
#pragma unroll
        for (int n = 0; n < NS; n++) {
            float4 k = __ldg(&cf[n]);
            float z0 = fmaf(k.y, in0, k.z);
            float z1 = fmaf(k.y, in1, k.z);
            float v0 = fmaf(k.x, st0[n], z0);
            float v1 = fmaf(k.x, st1[n], z1);
            st0[n] = v0; st1[n] = v1;
            s0 = fmaf(v0, k.w, s0);
            s1 = fmaf(v1, k.w, s1);
        }
        ob[t * TD + i]       = s0;
        ob[t * TD + i + 128] = s1;
    }
}

// ---------------------------------------------------------------------------
// metadata order: x[B*T*D], should_pop[D], sharpen_pointer[1],
//                 latch_enable[D], latch_init[B*D]  -> out[B*T*D] float32
// ---------------------------------------------------------------------------
extern "C" void kernel_launch(void* const* d_in, const int* in_sizes, int n_in,
                              void* d_out, int out_size)
{
    const float* x   = (const float*)d_in[0];
    const float* sp  = (const float*)d_in[1];
    const float* shp = (const float*)d_in[2];
    const float* le  = (const float*)d_in[3];
    const float* li  = (const float*)d_in[4];
    float* out = (float*)d_out;

    precompute_g_kernel<<<(BB * TT) / 8, 256>>>(x, le);
    pointer_scan_kernel<<<BB, 32>>>(x, sp, shp, li);
    stack_kernel<<<BB, 128>>>(x, out);
}